// round 6
// baseline (speedup 1.0000x reference)
#include <cuda_runtime.h>
#include <cstdint>

// ---------------- device scratch ----------------
__device__ __align__(16) float g_act0[32 * 21504];
__device__ __align__(16) float g_act1[32 * 16384];
__device__ __align__(16) float g_act2[32 * 4096];
__device__ __align__(16) float g_act3[32 * 4096];
__device__ __align__(16) float g_act4[32 * 64];
__device__ __align__(16) float g_part[4 * 32 * 4096];

// ---------------- PTX helpers ----------------
__device__ __forceinline__ unsigned smem_u32(const void* p) {
    return (unsigned)__cvta_generic_to_shared(p);
}
__device__ __forceinline__ void mbar_init(unsigned a, unsigned cnt) {
    asm volatile("mbarrier.init.shared.b64 [%0], %1;" :: "r"(a), "r"(cnt) : "memory");
}
__device__ __forceinline__ void mbar_expect(unsigned a, unsigned bytes) {
    asm volatile("mbarrier.arrive.expect_tx.shared.b64 _, [%0], %1;" :: "r"(a), "r"(bytes) : "memory");
}
__device__ __forceinline__ void mbar_wait(unsigned a, unsigned parity) {
    unsigned done;
    asm volatile("{\n\t.reg .pred p;\n\t"
                 "mbarrier.try_wait.parity.shared.b64 p, [%1], %2;\n\t"
                 "selp.b32 %0, 1, 0, p;\n\t}"
                 : "=r"(done) : "r"(a), "r"(parity) : "memory");
    if (!done) {
        asm volatile("{\n\t.reg .pred P1;\n\t"
                     "W_%=:\n\t"
                     "mbarrier.try_wait.parity.shared.b64 P1, [%0], %1, 0x989680;\n\t"
                     "@P1 bra.uni D_%=;\n\t"
                     "bra.uni W_%=;\n\t"
                     "D_%=:\n\t}" :: "r"(a), "r"(parity) : "memory");
    }
}
__device__ __forceinline__ void bulk_g2s(unsigned dst, const void* src, unsigned bytes, unsigned mbar) {
    asm volatile("cp.async.bulk.shared::cluster.global.mbarrier::complete_tx::bytes [%0], [%1], %2, [%3];"
                 :: "r"(dst), "l"(src), "r"(bytes), "r"(mbar) : "memory");
}
__device__ __forceinline__ void ldsm4(unsigned &r0, unsigned &r1, unsigned &r2, unsigned &r3, unsigned a) {
    asm volatile("ldmatrix.sync.aligned.m8n8.x4.shared.b16 {%0,%1,%2,%3}, [%4];"
                 : "=r"(r0), "=r"(r1), "=r"(r2), "=r"(r3) : "r"(a));
}
__device__ __forceinline__ void mma16816(float* d, unsigned a0, unsigned a1, unsigned a2, unsigned a3,
                                         unsigned b0, unsigned b1) {
    asm volatile("mma.sync.aligned.m16n8k16.row.col.f32.bf16.bf16.f32 "
                 "{%0,%1,%2,%3}, {%4,%5,%6,%7}, {%8,%9}, {%0,%1,%2,%3};"
                 : "+f"(d[0]), "+f"(d[1]), "+f"(d[2]), "+f"(d[3])
                 : "r"(a0), "r"(a1), "r"(a2), "r"(a3), "r"(b0), "r"(b1));
}

// smem layout (bytes)
#define OFF_BAR    0         // 3 x 8B mbarriers
#define OFF_STAGE  1024      // 3 stages x 49152 (96 rows x 512B fp32)
#define STAGE_SZ   49152
#define OFF_TILES  (OFF_STAGE + 3 * STAGE_SZ)       // 148480
#define WH_OFF     0                                 // 64 x 272B bf16 (stride 136 elems)
#define WL_OFF     17408
#define XH_OFF     34816                             // 32 x 272B
#define XL_OFF     43520
#define SMEM_TOTAL (OFF_TILES + 52224)               // 200704

// ---------------- conv + permuted scatter ----------------
__global__ void conv_kernel(const float* __restrict__ in,
                            const float* __restrict__ cw,
                            const float* __restrict__ cb) {
    int b = blockIdx.x >> 2, f = blockIdx.x & 3, tid = threadIdx.x;
    __shared__ float xin[343], wsh[128], bsh[16];
    for (int i = tid; i < 343; i += 128) xin[i] = in[(b * 343 + i) * 5 + f];
    if (tid < 128) wsh[tid] = cw[tid];
    if (tid < 16)  bsh[tid] = cb[tid];
    __syncthreads();
    int h = b >> 4, base = (b & 15) * 1344 + f * 336;
    for (int l = tid; l < 336; l += 128) {
        #pragma unroll
        for (int c = 0; c < 16; ++c) {
            float s = bsh[c];
            #pragma unroll
            for (int k = 0; k < 8; ++k) s += xin[l + k] * wsh[c * 8 + k];
            g_act0[(2 * c + h) * 21504 + base + l] = fmaxf(s, 0.f);
        }
    }
}

// ---------------- bf16x3 mma.sync GEMM ----------------
// D[n(neuron), b(batch)] = sum_k W[n,k] * X[b,k];  tile = 64 neurons x 32 batch, slab k=128.
__device__ __forceinline__ const float* act_in(int s) {
    return s == 0 ? g_act0 : s == 1 ? g_act1 : g_act2;
}

__global__ __launch_bounds__(256, 1)
void gemm_mma(int xsel, const float* __restrict__ W, const float* __restrict__ bias,
              float* __restrict__ outp, int N, int K, int nslabs, int split) {
    extern __shared__ __align__(1024) char smem[];
    unsigned sb = smem_u32(smem);
    const float* X = act_in(xsel);
    int tid = threadIdx.x, wid = tid >> 5, lane = tid & 31;
    int tile = blockIdx.x, ky = blockIdx.y;
    long k0 = (long)ky * nslabs * 128;

    if (tid == 0)
        for (int i = 0; i < 3; ++i) mbar_init(sb + OFF_BAR + 8 * i, 1);
    __syncthreads();

    const float* Wt = W + (long)tile * 64 * K + k0;
    const float* Xt = X + k0;

    auto load_slab = [&](int s) {
        unsigned st = sb + OFF_STAGE + (s % 3) * STAGE_SZ;
        unsigned mb = sb + OFF_BAR + 8 * (s % 3);
        if (lane == 0) mbar_expect(mb, 49152);
        __syncwarp();
        long koff = (long)s * 128;
        #pragma unroll
        for (int r = lane; r < 96; r += 32) {
            const float* src = (r < 64) ? (Wt + (long)r * K + koff)
                                        : (Xt + (long)(r - 64) * K + koff);
            bulk_g2s(st + r * 512, src, 512, mb);
        }
    };

    if (wid == 0)
        for (int s = 0; s < 3 && s < nslabs; ++s) load_slab(s);

    // mma thread mapping
    int m0 = (wid & 3) * 16, nh = (wid >> 2) * 16;
    int g = lane >> 2, t = lane & 3;
    unsigned tb = sb + OFF_TILES;
    unsigned aoff = ((m0 + (lane & 15)) * 136 + (lane >> 4) * 8) * 2;
    unsigned boff = ((nh + (lane & 7) + ((lane >> 3) & 1) * 8) * 136 + (lane >> 4) * 8) * 2;

    float acc[2][4] = {{0.f, 0.f, 0.f, 0.f}, {0.f, 0.f, 0.f, 0.f}};
    int fph[3] = {0, 0, 0};

    for (int s = 0; s < nslabs; ++s) {
        int fb = s % 3;
        mbar_wait(sb + OFF_BAR + 8 * fb, fph[fb]); fph[fb] ^= 1;

        // convert fp32 stage -> bf16 hi/lo tiles
        const float* stage = (const float*)(smem + OFF_STAGE + fb * STAGE_SZ);
        #pragma unroll
        for (int it = 0; it < 12; ++it) {
            int q = it * 256 + tid;          // 0..3071
            int row = q >> 5, c4 = q & 31;
            float4 v = *(const float4*)(stage + row * 128 + c4 * 4);
            unsigned h01, h23, l01, l23;
            asm("cvt.rn.bf16x2.f32 %0, %1, %2;" : "=r"(h01) : "f"(v.y), "f"(v.x));
            asm("cvt.rn.bf16x2.f32 %0, %1, %2;" : "=r"(h23) : "f"(v.w), "f"(v.z));
            float r0 = v.x - __uint_as_float(h01 << 16);
            float r1 = v.y - __uint_as_float(h01 & 0xffff0000u);
            float r2 = v.z - __uint_as_float(h23 << 16);
            float r3 = v.w - __uint_as_float(h23 & 0xffff0000u);
            asm("cvt.rn.bf16x2.f32 %0, %1, %2;" : "=r"(l01) : "f"(r1), "f"(r0));
            asm("cvt.rn.bf16x2.f32 %0, %1, %2;" : "=r"(l23) : "f"(r3), "f"(r2));
            unsigned dhi, dlo;
            if (row < 64) {
                dhi = tb + WH_OFF + row * 272 + c4 * 8;
                dlo = tb + WL_OFF + row * 272 + c4 * 8;
            } else {
                dhi = tb + XH_OFF + (row - 64) * 272 + c4 * 8;
                dlo = tb + XL_OFF + (row - 64) * 272 + c4 * 8;
            }
            asm volatile("st.shared.v2.b32 [%0], {%1,%2};" :: "r"(dhi), "r"(h01), "r"(h23));
            asm volatile("st.shared.v2.b32 [%0], {%1,%2};" :: "r"(dlo), "r"(l01), "r"(l23));
        }
        __syncthreads();

        if (wid == 0 && s + 3 < nslabs) load_slab(s + 3);

        #pragma unroll
        for (int ks = 0; ks < 8; ++ks) {
            unsigned kb = ks * 32;
            unsigned ah0, ah1, ah2, ah3, al0, al1, al2, al3;
            unsigned bh0, bh1, bh2, bh3, bl0, bl1, bl2, bl3;
            ldsm4(ah0, ah1, ah2, ah3, tb + WH_OFF + aoff + kb);
            ldsm4(al0, al1, al2, al3, tb + WL_OFF + aoff + kb);
            ldsm4(bh0, bh1, bh2, bh3, tb + XH_OFF + boff + kb);
            ldsm4(bl0, bl1, bl2, bl3, tb + XL_OFF + boff + kb);
            // frag0: b0=bh0/bl0, b1=bh2/bl2 ; frag1: b0=bh1/bl1, b1=bh3/bl3
            mma16816(acc[0], ah0, ah1, ah2, ah3, bh0, bh2);
            mma16816(acc[0], ah0, ah1, ah2, ah3, bl0, bl2);
            mma16816(acc[0], al0, al1, al2, al3, bh0, bh2);
            mma16816(acc[1], ah0, ah1, ah2, ah3, bh1, bh3);
            mma16816(acc[1], ah0, ah1, ah2, ah3, bl1, bl3);
            mma16816(acc[1], al0, al1, al2, al3, bh1, bh3);
        }
        __syncthreads();
    }

    // epilogue: D fragment (row=neuron g/g+8, col=batch 2t/2t+1 within n-frag)
    int n0 = tile * 64 + m0 + g;
    #pragma unroll
    for (int nf = 0; nf < 2; ++nf) {
        int b0 = nh + nf * 8 + 2 * t;
        if (split) {
            g_part[(long)(ky * 32 + b0)     * N + n0]     = acc[nf][0];
            g_part[(long)(ky * 32 + b0 + 1) * N + n0]     = acc[nf][1];
            g_part[(long)(ky * 32 + b0)     * N + n0 + 8] = acc[nf][2];
            g_part[(long)(ky * 32 + b0 + 1) * N + n0 + 8] = acc[nf][3];
        } else {
            float bv0 = bias[n0], bv8 = bias[n0 + 8];
            outp[(long)b0       * N + n0]     = fmaxf(acc[nf][0] + bv0, 0.f);
            outp[(long)(b0 + 1) * N + n0]     = fmaxf(acc[nf][1] + bv0, 0.f);
            outp[(long)b0       * N + n0 + 8] = fmaxf(acc[nf][2] + bv8, 0.f);
            outp[(long)(b0 + 1) * N + n0 + 8] = fmaxf(acc[nf][3] + bv8, 0.f);
        }
    }
}

// ---------------- split-K reduce + bias + relu ----------------
__global__ void reduce_kernel(const float* __restrict__ bias, int osel, int N, int ks) {
    int idx = blockIdx.x * 256 + threadIdx.x;
    if (idx >= 32 * N) return;
    float s = bias[idx % N];
    for (int si = 0; si < ks; ++si) s += g_part[(long)si * 32 * N + idx];
    float* out = (osel == 2) ? g_act2 : g_act3;
    out[idx] = fmaxf(s, 0.f);
}

// ---------------- dense4 (4096 -> 64) ----------------
__global__ void dense4_kernel(const float* __restrict__ w4, const float* __restrict__ b4) {
    int n = blockIdx.x, tid = threadIdx.x;
    float acc[32];
    #pragma unroll
    for (int b = 0; b < 32; ++b) acc[b] = 0.f;
    const float* wr = w4 + n * 4096;
    for (int k = tid; k < 4096; k += 128) {
        float w = wr[k];
        #pragma unroll
        for (int b = 0; b < 32; ++b) acc[b] += g_act3[b * 4096 + k] * w;
    }
    __shared__ float red[4][32];
    int lane = tid & 31, wrp = tid >> 5;
    #pragma unroll
    for (int b = 0; b < 32; ++b) {
        float v = acc[b];
        v += __shfl_down_sync(0xffffffffu, v, 16);
        v += __shfl_down_sync(0xffffffffu, v, 8);
        v += __shfl_down_sync(0xffffffffu, v, 4);
        v += __shfl_down_sync(0xffffffffu, v, 2);
        v += __shfl_down_sync(0xffffffffu, v, 1);
        if (lane == 0) red[wrp][b] = v;
    }
    __syncthreads();
    if (tid < 32) {
        float s = red[0][tid] + red[1][tid] + red[2][tid] + red[3][tid] + b4[n];
        g_act4[tid * 64 + n] = fmaxf(s, 0.f);
    }
}

// ---------------- fused output (64 -> 16 -> 1) ----------------
__global__ void final_kernel(const float* __restrict__ wo, const float* __restrict__ bo,
                             const float* __restrict__ wf, const float* __restrict__ bf,
                             float* __restrict__ out) {
    int b = threadIdx.x;   // 32 threads
    float res = bf[0];
    for (int j = 0; j < 16; ++j) {
        float o = bo[j];
        #pragma unroll
        for (int n = 0; n < 64; ++n) o += g_act4[b * 64 + n] * wo[j * 64 + n];
        res += o * wf[j];
    }
    out[b] = res;
}

extern "C" void kernel_launch(void* const* d_in, const int* in_sizes, int n_in,
                              void* d_out, int out_size) {
    const float* in  = (const float*)d_in[0];
    const float* cw  = (const float*)d_in[4];
    const float* cb  = (const float*)d_in[5];
    const float* w1  = (const float*)d_in[6];
    const float* b1  = (const float*)d_in[7];
    const float* w2  = (const float*)d_in[8];
    const float* b2  = (const float*)d_in[9];
    const float* w3  = (const float*)d_in[10];
    const float* b3  = (const float*)d_in[11];
    const float* w4  = (const float*)d_in[12];
    const float* b4  = (const float*)d_in[13];
    const float* wo  = (const float*)d_in[14];
    const float* bo  = (const float*)d_in[15];
    const float* wf  = (const float*)d_in[16];
    const float* bf  = (const float*)d_in[17];
    float* out = (float*)d_out;

    float* act1;
    cudaGetSymbolAddress((void**)&act1, g_act1);

    cudaFuncSetAttribute(gemm_mma, cudaFuncAttributeMaxDynamicSharedMemorySize, SMEM_TOTAL);

    conv_kernel<<<128, 128>>>(in, cw, cb);

    // dense1: 16384 x 21504, no split
    gemm_mma<<<dim3(256, 1), 256, SMEM_TOTAL>>>(0, w1, b1, act1, 16384, 21504, 168, 0);

    // dense2: 4096 x 16384, split-K 2
    gemm_mma<<<dim3(64, 2), 256, SMEM_TOTAL>>>(1, w2, nullptr, nullptr, 4096, 16384, 64, 1);
    reduce_kernel<<<512, 256>>>(b2, 2, 4096, 2);

    // dense3: 4096 x 4096, split-K 2
    gemm_mma<<<dim3(64, 2), 256, SMEM_TOTAL>>>(2, w3, nullptr, nullptr, 4096, 4096, 16, 1);
    reduce_kernel<<<512, 256>>>(b3, 3, 4096, 2);

    dense4_kernel<<<64, 128>>>(w4, b4);
    final_kernel<<<1, 32>>>(wo, bo, wf, bf, out);
}

// round 7
// speedup vs baseline: 1.7067x; 1.7067x over previous
#include <cuda_runtime.h>

#define KB 16
#define SW 20
#define BN 256
#define STAGES 4

__device__ __align__(16) float g_act0[32 * 21504];
__device__ __align__(16) float g_act1[32 * 16384];
__device__ __align__(16) float g_act2[32 * 4096];
__device__ __align__(16) float g_act3[32 * 4096];
__device__ __align__(16) float g_act4[32 * 64];
__device__ __align__(16) float g_part[16 * 32 * 4096]; // 2,097,152 == 4*32*16384

__device__ __forceinline__ void cp16(unsigned s, const float* g) {
    asm volatile("cp.async.cg.shared.global [%0], [%1], 16;" :: "r"(s), "l"(g));
}
__device__ __forceinline__ void lds_v2(unsigned long long &a, unsigned long long &b, unsigned addr) {
    asm("ld.shared.v2.b64 {%0, %1}, [%2];" : "=l"(a), "=l"(b) : "r"(addr));
}
__device__ __forceinline__ void fma2(unsigned long long &d, unsigned long long a, unsigned long long b) {
    asm("fma.rn.f32x2 %0, %1, %2, %0;" : "+l"(d) : "l"(a), "l"(b));
}

// ---------------- conv + permuted scatter (split into 5 launches) ----------------
__global__ void conv_kernel(const float* __restrict__ in,
                            const float* __restrict__ cw,
                            const float* __restrict__ cb, int off) {
    int bf = blockIdx.x + off;
    if (bf >= 128) return;
    int b = bf >> 2, f = bf & 3, tid = threadIdx.x;
    __shared__ float xin[343], wsh[128], bsh[16];
    for (int i = tid; i < 343; i += 128) xin[i] = in[(b * 343 + i) * 5 + f];
    if (tid < 128) wsh[tid] = cw[tid];
    if (tid < 16)  bsh[tid] = cb[tid];
    __syncthreads();
    int h = b >> 4, base = (b & 15) * 1344 + f * 336;
    for (int l = tid; l < 336; l += 128) {
        #pragma unroll
        for (int c = 0; c < 16; ++c) {
            float s = bsh[c];
            #pragma unroll
            for (int k = 0; k < 8; ++k) s += xin[l + k] * wsh[c * 8 + k];
            g_act0[(2 * c + h) * 21504 + base + l] = fmaxf(s, 0.f);
        }
    }
}

// ---------------- fp32x2 GEMM, 256 thr, 8x4 microtile, 4-stage, 2 CTA/SM ----------------
__device__ __forceinline__ const float* act_ptr(int s) {
    return s == 0 ? g_act0 : s == 1 ? g_act1 : s == 2 ? g_act2 : g_act3;
}

__global__ __launch_bounds__(256, 2)
void gemm_kernel(int xsel, const float* __restrict__ W, int N, int K, int nsteps) {
    extern __shared__ __align__(16) float smem[];
    const int STB = (BN + 32) * SW;            // floats per stage = 5760
    const float* X = act_ptr(xsel);
    int tid = threadIdx.x, ntile = blockIdx.x * BN, ky = blockIdx.y;
    long k0 = (long)ky * nsteps * KB;
    int ng = tid & 63;             // n = ng + 64*j, j<4
    int b0 = (tid >> 6) * 8;       // 4 groups of 8 batch rows
    unsigned sm_b = (unsigned)__cvta_generic_to_shared(smem);

    unsigned long long acc[8][4];
    #pragma unroll
    for (int i = 0; i < 8; ++i)
        #pragma unroll
        for (int j = 0; j < 4; ++j) acc[i][j] = 0ull;

    const float* Wt = W + (long)ntile * K + k0;
    const float* Xt = X + k0;

    auto stage = [&](int c) {
        int buf = ((unsigned)c) % STAGES;
        long kc = (long)c * KB;
        unsigned wd = sm_b + buf * (STB * 4);
        unsigned xd = wd + BN * SW * 4;
        #pragma unroll
        for (int it = 0; it < 4; ++it) {         // 256 rows * 4 quads / 256 thr
            int o = it * 256 + tid, n = o >> 2, kq = o & 3;
            cp16(wd + (n * SW + kq * 4) * 4, Wt + (long)n * K + kc + kq * 4);
        }
        if (tid < 128) {
            int b = tid >> 2, kq = tid & 3;
            cp16(xd + (b * SW + kq * 4) * 4, Xt + (long)b * K + kc + kq * 4);
        }
    };

    for (int c = 0; c < 3; ++c) {
        if (c < nsteps) stage(c);
        asm volatile("cp.async.commit_group;");
    }

    for (int c = 0; c < nsteps; ++c) {
        asm volatile("cp.async.wait_group 2;");
        __syncthreads();
        if (c + 3 < nsteps) stage(c + 3);
        asm volatile("cp.async.commit_group;");

        int buf = ((unsigned)c) % STAGES;
        unsigned wsa = sm_b + buf * (STB * 4);
        unsigned xsa = wsa + BN * SW * 4;
        #pragma unroll
        for (int kk = 0; kk < KB; kk += 4) {
            unsigned long long xa[8], xb[8];
            #pragma unroll
            for (int i = 0; i < 8; ++i)
                lds_v2(xa[i], xb[i], xsa + ((b0 + i) * SW + kk) * 4);  // warp-broadcast
            #pragma unroll
            for (int j = 0; j < 4; ++j) {
                unsigned long long wa, wb;
                lds_v2(wa, wb, wsa + ((ng + 64 * j) * SW + kk) * 4);
                #pragma unroll
                for (int i = 0; i < 8; ++i) {
                    fma2(acc[i][j], xa[i], wa);
                    fma2(acc[i][j], xb[i], wb);
                }
            }
        }
    }

    #pragma unroll
    for (int i = 0; i < 8; ++i)
        #pragma unroll
        for (int j = 0; j < 4; ++j) {
            unsigned long long v = acc[i][j];
            float s = __uint_as_float((unsigned)v) + __uint_as_float((unsigned)(v >> 32));
            g_part[((long)(ky * 32 + b0 + i)) * N + ntile + ng + 64 * j] = s;
        }
}

// ---------------- split-K reduce + bias + relu ----------------
__global__ void reduce_kernel(const float* __restrict__ bias, int osel, int N, int ks) {
    int idx = blockIdx.x * 256 + threadIdx.x;
    if (idx >= 32 * N) return;
    float s = bias[idx % N];
    for (int si = 0; si < ks; ++si) s += g_part[(long)si * 32 * N + idx];
    float* out = (osel == 1) ? g_act1 : (osel == 2) ? g_act2 : g_act3;
    out[idx] = fmaxf(s, 0.f);
}

// ---------------- dense4 (4096 -> 64) ----------------
__global__ void dense4_kernel(const float* __restrict__ w4, const float* __restrict__ b4) {
    int n = blockIdx.x, tid = threadIdx.x;
    float acc[32];
    #pragma unroll
    for (int b = 0; b < 32; ++b) acc[b] = 0.f;
    const float* wr = w4 + n * 4096;
    for (int k = tid; k < 4096; k += 128) {
        float w = wr[k];
        #pragma unroll
        for (int b = 0; b < 32; ++b) acc[b] += g_act3[b * 4096 + k] * w;
    }
    __shared__ float red[4][32];
    int lane = tid & 31, wrp = tid >> 5;
    #pragma unroll
    for (int b = 0; b < 32; ++b) {
        float v = acc[b];
        v += __shfl_down_sync(0xffffffffu, v, 16);
        v += __shfl_down_sync(0xffffffffu, v, 8);
        v += __shfl_down_sync(0xffffffffu, v, 4);
        v += __shfl_down_sync(0xffffffffu, v, 2);
        v += __shfl_down_sync(0xffffffffu, v, 1);
        if (lane == 0) red[wrp][b] = v;
    }
    __syncthreads();
    if (tid < 32) {
        float s = red[0][tid] + red[1][tid] + red[2][tid] + red[3][tid] + b4[n];
        g_act4[tid * 64 + n] = fmaxf(s, 0.f);
    }
}

// ---------------- fused output (64 -> 16 -> 1) ----------------
__global__ void final_kernel(const float* __restrict__ wo, const float* __restrict__ bo,
                             const float* __restrict__ wf, const float* __restrict__ bf,
                             float* __restrict__ out) {
    int b = threadIdx.x;   // 32 threads
    float res = bf[0];
    for (int j = 0; j < 16; ++j) {
        float o = bo[j];
        #pragma unroll
        for (int n = 0; n < 64; ++n) o += g_act4[b * 64 + n] * wo[j * 64 + n];
        res += o * wf[j];
    }
    out[b] = res;
}

extern "C" void kernel_launch(void* const* d_in, const int* in_sizes, int n_in,
                              void* d_out, int out_size) {
    const float* in  = (const float*)d_in[0];
    const float* cw  = (const float*)d_in[4];
    const float* cb  = (const float*)d_in[5];
    const float* w1  = (const float*)d_in[6];
    const float* b1  = (const float*)d_in[7];
    const float* w2  = (const float*)d_in[8];
    const float* b2  = (const float*)d_in[9];
    const float* w3  = (const float*)d_in[10];
    const float* b3  = (const float*)d_in[11];
    const float* w4  = (const float*)d_in[12];
    const float* b4  = (const float*)d_in[13];
    const float* wo  = (const float*)d_in[14];
    const float* bo  = (const float*)d_in[15];
    const float* wf  = (const float*)d_in[16];
    const float* bf  = (const float*)d_in[17];
    float* out = (float*)d_out;

    int smem = STAGES * (BN + 32) * SW * 4;   // 92,160 B -> 2 CTAs/SM
    cudaFuncSetAttribute(gemm_kernel, cudaFuncAttributeMaxDynamicSharedMemorySize, smem);

    // conv split into 5 launches (same total work) so the dense1 GEMM is launch #6 for ncu -s 5
    for (int off = 0; off < 128; off += 26)
        conv_kernel<<<26, 128>>>(in, cw, cb, off);

    // dense1: 16384 x 21504, 64 tiles x split 4 = 256 CTAs
    gemm_kernel<<<dim3(64, 4), 256, smem>>>(0, w1, 16384, 21504, 336);
    reduce_kernel<<<2048, 256>>>(b1, 1, 16384, 4);

    // dense2: 4096 x 16384, 16 tiles x split 16 = 256 CTAs
    gemm_kernel<<<dim3(16, 16), 256, smem>>>(1, w2, 4096, 16384, 64);
    reduce_kernel<<<512, 256>>>(b2, 2, 4096, 16);

    // dense3: 4096 x 4096, 16 tiles x split 16 = 256 CTAs
    gemm_kernel<<<dim3(16, 16), 256, smem>>>(2, w3, 4096, 4096, 16);
    reduce_kernel<<<512, 256>>>(b3, 3, 4096, 16);

    dense4_kernel<<<64, 128>>>(w4, b4);
    final_kernel<<<1, 32>>>(wo, bo, wf, bf, out);
}